// round 14
// baseline (speedup 1.0000x reference)
#include <cuda_runtime.h>

#define NANCH 8400
#define BATCH 32
#define NCLS  80
#define BINS  16
#define LN2   0.69314718f

// [0]=cls_sum [1]=iou_sum [2]=dfl_sum [3]=pos_count
__device__ double g_acc[4];
__device__ unsigned int g_done;

__device__ __forceinline__ float tanh_fast(float x) {
    float y;
    asm("tanh.approx.f32 %0, %1;" : "=f"(y) : "f"(x));
    return y;
}

// returns sigmoid(s)^2 * log2(sigmoid(-s));  focal t=0 elem = -0.75*ln2 * this
__device__ __forceinline__ float cls_neg_raw(float s) {
    float t = tanh_fast(0.5f * s);
    float u = 0.5f - 0.5f * t;           // sigmoid(-s)
    float p = 0.5f + 0.5f * t;           // sigmoid(s)
    return p * p * __log2f(u);
}

template<int HW, int W, int STRIDE, int AOFS>
__device__ __forceinline__ void process_scale(
    const float* __restrict__ p, const float* __restrict__ gtb,
    const int* __restrict__ gtl, const int* __restrict__ mind,
    int tile, float& cls_s, float& iou_s, float& dfl_s, int& cnt)
{
    const int tid = threadIdx.x;
    const int g   = tid >> 6;          // channel group 0..3 (20 channels each)
    const int t   = tid & 63;          // anchor quad 0..63

    const int a   = tile * 256 + 4 * t;          // first anchor of this quad (mult of 4)
    const int img = a / HW;                      // quad never crosses img (HW % 4 == 0)
    const int hw  = a - img * HW;

    const float* base  = p + (size_t)img * 144 * HW + hw;
    const float* cbase = base + (64 + g * 20) * HW;

    // ---------- classification: 20 x float4 (4 anchors), coalesced 16B loads ----------
    float c0 = 0.f, c1 = 0.f, c2 = 0.f, c3 = 0.f;
    #pragma unroll
    for (int c = 0; c < 20; ++c) {
        float4 v = *reinterpret_cast<const float4*>(cbase + c * HW);
        c0 += cls_neg_raw(v.x);
        c1 += cls_neg_raw(v.y);
        c2 += cls_neg_raw(v.z);
        c3 += cls_neg_raw(v.w);
    }
    cls_s = ((c0 + c1) + (c2 + c3)) * (-0.75f * LN2);

    // ---------- positives: channel-group 0 threads own their quad ----------
    if (g == 0) {
        const int4 mi = *reinterpret_cast<const int4*>(mind + img * NANCH + AOFS + hw);
        const int inds[4] = { mi.x, mi.y, mi.z, mi.w };
        const float* ccls = base + 64 * HW;

        #pragma unroll
        for (int j = 0; j < 4; ++j) {
            const int ind = inds[j];
            if (ind < 0) continue;
            cnt++;
            const int lbl = gtl[img * 32 + ind];

            // swap t=0 -> t=1 element on the label channel
            {
                float s = ccls[lbl * HW + j];
                float th = tanh_fast(0.5f * s);
                float u = 0.5f - 0.5f * th;
                float q = 0.5f + 0.5f * th;
                float elem0 = -0.75f * LN2 * q * q * __log2f(u);
                float elem1 = -0.25f * LN2 * u * u * __log2f(q);
                cls_s += elem1 - elem0;
            }

            const float* tb4 = gtb + (size_t)(img * 32 + ind) * 4;
            float tx1 = tb4[0], ty1 = tb4[1], tx2 = tb4[2], ty2 = tb4[3];

            const int hwj = hw + j;
            const int wy = hwj / W, wx = hwj - wy * W;
            const float gx = (wx + 0.5f) * (float)STRIDE;
            const float gy = (wy + 0.5f) * (float)STRIDE;

            float tgt[4] = { fmaxf(gx - tx1, 0.f), fmaxf(gy - ty1, 0.f),
                             fmaxf(tx2 - gx, 0.f), fmaxf(ty2 - gy, 0.f) };
            float d[4];

            #pragma unroll
            for (int k = 0; k < 4; ++k) {
                float tb = fminf(tgt[k] * (1.f / (float)STRIDE), 15.f - 1e-6f);
                int   lo = (int)tb;
                int   hi = min(lo + 1, BINS - 1);
                float aa = tb - (float)lo;

                float S = 0.f, E = 0.f, vlo = 0.f, vhi = 0.f;
                #pragma unroll
                for (int jj = 0; jj < BINS; ++jj) {
                    float v = base[(k * BINS + jj) * HW + j];
                    float e = __expf(v);
                    S += e;
                    E += e * (float)jj;
                    vlo = (jj == lo) ? v : vlo;
                    vhi = (jj == hi) ? v : vhi;
                }
                d[k] = __fdividef(E, S) * (float)STRIDE;
                float lS = __logf(S);
                dfl_s -= (1.f - aa) * (vlo - lS) + aa * (vhi - lS);
            }

            float px1 = gx - d[0], py1 = gy - d[1];
            float px2 = gx + d[2], py2 = gy + d[3];
            float ix1 = fmaxf(px1, tx1), iy1 = fmaxf(py1, ty1);
            float ix2 = fminf(px2, tx2), iy2 = fminf(py2, ty2);
            float inter  = fmaxf(ix2 - ix1, 0.f) * fmaxf(iy2 - iy1, 0.f);
            float area_p = fmaxf(px2 - px1, 0.f) * fmaxf(py2 - py1, 0.f);
            float area_t = fmaxf(tx2 - tx1, 0.f) * fmaxf(ty2 - ty1, 0.f);
            float iou = inter / (area_p + area_t - inter + 1e-7f);
            iou_s += 1.f - iou;
        }
    }
}

__global__ void __launch_bounds__(256, 8) yolo_loss_kernel(
    const float* __restrict__ p0, const float* __restrict__ p1, const float* __restrict__ p2,
    const float* __restrict__ gtb, const int* __restrict__ gtl, const int* __restrict__ mind,
    float* __restrict__ out, int out_n)
{
    float cls_s = 0.f, iou_s = 0.f, dfl_s = 0.f;
    int cnt = 0;

    const int tile = blockIdx.x;
    if (tile < 800) {
        process_scale<6400, 80,  8, 0>(p0, gtb, gtl, mind, tile,        cls_s, iou_s, dfl_s, cnt);
    } else if (tile < 1000) {
        process_scale<1600, 40, 16, 6400>(p1, gtb, gtl, mind, tile - 800,  cls_s, iou_s, dfl_s, cnt);
    } else {
        process_scale< 400, 20, 32, 8000>(p2, gtb, gtl, mind, tile - 1000, cls_s, iou_s, dfl_s, cnt);
    }

    // ---------- block reduction ----------
    #pragma unroll
    for (int o = 16; o > 0; o >>= 1) {
        cls_s += __shfl_down_sync(0xffffffffu, cls_s, o);
        iou_s += __shfl_down_sync(0xffffffffu, iou_s, o);
        dfl_s += __shfl_down_sync(0xffffffffu, dfl_s, o);
        cnt   += __shfl_down_sync(0xffffffffu, cnt,   o);
    }

    __shared__ float sc[8], si[8], sd[8];
    __shared__ int   sp[8];
    int lane = threadIdx.x & 31;
    int warp = threadIdx.x >> 5;
    if (lane == 0) { sc[warp] = cls_s; si[warp] = iou_s; sd[warp] = dfl_s; sp[warp] = cnt; }
    __syncthreads();

    if (warp == 0 && lane == 0) {
        cls_s = 0.f; iou_s = 0.f; dfl_s = 0.f; cnt = 0;
        #pragma unroll
        for (int w = 0; w < 8; ++w) {
            cls_s += sc[w]; iou_s += si[w]; dfl_s += sd[w]; cnt += sp[w];
        }

        atomicAdd(&g_acc[0], (double)cls_s);
        atomicAdd(&g_acc[1], (double)iou_s);
        atomicAdd(&g_acc[2], (double)dfl_s);
        atomicAdd(&g_acc[3], (double)cnt);

        __threadfence();
        unsigned int ticket = atomicAdd(&g_done, 1u);
        if (ticket == gridDim.x - 1) {
            double v0 = atomicAdd(&g_acc[0], 0.0);
            double v1 = atomicAdd(&g_acc[1], 0.0);
            double v2 = atomicAdd(&g_acc[2], 0.0);
            double v3 = atomicAdd(&g_acc[3], 0.0);
            double np = v3 < 1.0 ? 1.0 : v3;
            double total = v0 / np + 7.5 * v1 / np + 1.5 * v2 / (np * 4.0);
            for (int i = 0; i < out_n; ++i) out[i] = (float)total;
            g_acc[0] = 0.0; g_acc[1] = 0.0; g_acc[2] = 0.0; g_acc[3] = 0.0;
            __threadfence();
            g_done = 0u;
        }
    }
}

extern "C" void kernel_launch(void* const* d_in, const int* in_sizes, int n_in,
                              void* d_out, int out_size) {
    const float* p0   = (const float*)d_in[0];
    const float* p1   = (const float*)d_in[1];
    const float* p2   = (const float*)d_in[2];
    const float* gtb  = (const float*)d_in[3];
    const int*   gtl  = (const int*)d_in[4];
    const int*   mind = (const int*)d_in[5];
    float* out = (float*)d_out;

    // 800 + 200 + 50 = 1050 blocks; one wave at 8 blocks/SM
    yolo_loss_kernel<<<1050, 256>>>(p0, p1, p2, gtb, gtl, mind, out, out_size);
}

// round 15
// speedup vs baseline: 2.5998x; 2.5998x over previous
#include <cuda_runtime.h>

#define NANCH 8400
#define BATCH 32
#define NCLS  80
#define BINS  16
#define LN2   0.69314718f

// [0]=cls_sum [1]=iou_sum [2]=dfl_sum [3]=pos_count
__device__ double g_acc[4];
__device__ unsigned int g_done;

__device__ __forceinline__ float tanh_fast(float x) {
    float y;
    asm("tanh.approx.f32 %0, %1;" : "=f"(y) : "f"(x));
    return y;
}

// returns sigmoid(s)^2 * log2(sigmoid(-s));  focal t=0 elem = -0.75*ln2 * this
__device__ __forceinline__ float cls_neg_raw(float s) {
    float t = tanh_fast(0.5f * s);
    float u = 0.5f - 0.5f * t;           // sigmoid(-s)
    float p = 0.5f + 0.5f * t;           // sigmoid(s)
    return p * p * __log2f(u);
}

template<int HW, int W, int STRIDE, int AOFS>
__device__ __forceinline__ void process_scale(
    const float* __restrict__ p, const float* __restrict__ gtb,
    const int* __restrict__ gtl, const int* __restrict__ mind,
    int tile, float& cls_s, float& iou_s, float& dfl_s, int& pos_flag)
{
    const int i   = tile * 128 + threadIdx.x;
    const int img = i / HW;
    const int hw  = i - img * HW;

    const int ind = mind[img * NANCH + AOFS + hw];   // issue early

    const float* base  = p + (size_t)img * 144 * HW + hw;
    const float* cbase = base + 64 * HW;

    // ---------- classification: 80 channels, imm offsets, streaming loads ----------
    float c0 = 0.f, c1 = 0.f, c2 = 0.f, c3 = 0.f;
    #pragma unroll
    for (int c = 0; c < NCLS; c += 4) {
        float s0 = __ldcs(cbase + (c + 0) * HW);
        float s1 = __ldcs(cbase + (c + 1) * HW);
        float s2 = __ldcs(cbase + (c + 2) * HW);
        float s3 = __ldcs(cbase + (c + 3) * HW);
        c0 += cls_neg_raw(s0);
        c1 += cls_neg_raw(s1);
        c2 += cls_neg_raw(s2);
        c3 += cls_neg_raw(s3);
    }
    cls_s = ((c0 + c1) + (c2 + c3)) * (-0.75f * LN2);

    // ---------- positives: inline, divergent (~5% of lanes) ----------
    if (ind >= 0) {
        pos_flag = 1;
        int lbl = gtl[img * 32 + ind];

        // swap t=0 -> t=1 element on the label channel
        {
            float s = cbase[lbl * HW];
            float t = tanh_fast(0.5f * s);
            float u = 0.5f - 0.5f * t;
            float q = 0.5f + 0.5f * t;
            float elem0 = -0.75f * LN2 * q * q * __log2f(u);
            float elem1 = -0.25f * LN2 * u * u * __log2f(q);
            cls_s += elem1 - elem0;
        }

        const float* tb4 = gtb + (size_t)(img * 32 + ind) * 4;
        float tx1 = tb4[0], ty1 = tb4[1], tx2 = tb4[2], ty2 = tb4[3];

        int wy = hw / W, wx = hw - wy * W;
        float gx = (wx + 0.5f) * (float)STRIDE;
        float gy = (wy + 0.5f) * (float)STRIDE;

        float tgt[4] = { fmaxf(gx - tx1, 0.f), fmaxf(gy - ty1, 0.f),
                         fmaxf(tx2 - gx, 0.f), fmaxf(ty2 - gy, 0.f) };
        float d[4];

        #pragma unroll
        for (int k = 0; k < 4; ++k) {
            float tb = fminf(tgt[k] * (1.f / (float)STRIDE), 15.f - 1e-6f);
            int   lo = (int)tb;
            int   hi = min(lo + 1, BINS - 1);
            float aa = tb - (float)lo;

            float S = 0.f, E = 0.f, vlo = 0.f, vhi = 0.f;
            #pragma unroll
            for (int jj = 0; jj < BINS; ++jj) {
                float v = base[(k * BINS + jj) * HW];
                float e = __expf(v);
                S += e;
                E += e * (float)jj;
                vlo = (jj == lo) ? v : vlo;
                vhi = (jj == hi) ? v : vhi;
            }
            d[k] = __fdividef(E, S) * (float)STRIDE;
            float lS = __logf(S);
            dfl_s -= (1.f - aa) * (vlo - lS) + aa * (vhi - lS);
        }

        float px1 = gx - d[0], py1 = gy - d[1];
        float px2 = gx + d[2], py2 = gy + d[3];
        float ix1 = fmaxf(px1, tx1), iy1 = fmaxf(py1, ty1);
        float ix2 = fminf(px2, tx2), iy2 = fminf(py2, ty2);
        float inter  = fmaxf(ix2 - ix1, 0.f) * fmaxf(iy2 - iy1, 0.f);
        float area_p = fmaxf(px2 - px1, 0.f) * fmaxf(py2 - py1, 0.f);
        float area_t = fmaxf(tx2 - tx1, 0.f) * fmaxf(ty2 - ty1, 0.f);
        float iou = inter / (area_p + area_t - inter + 1e-7f);
        iou_s = 1.f - iou;
    }
}

__global__ void __launch_bounds__(128, 16) yolo_loss_kernel(
    const float* __restrict__ p0, const float* __restrict__ p1, const float* __restrict__ p2,
    const float* __restrict__ gtb, const int* __restrict__ gtl, const int* __restrict__ mind,
    float* __restrict__ out, int out_n)
{
    float cls_s = 0.f, iou_s = 0.f, dfl_s = 0.f;
    int pos_flag = 0;

    // 128-anchor tiles: scale0 = 1600 blocks, scale1 = 400, scale2 = 100
    const int tile = blockIdx.x;
    if (tile < 1600) {
        process_scale<6400, 80,  8, 0>(p0, gtb, gtl, mind, tile,        cls_s, iou_s, dfl_s, pos_flag);
    } else if (tile < 2000) {
        process_scale<1600, 40, 16, 6400>(p1, gtb, gtl, mind, tile - 1600, cls_s, iou_s, dfl_s, pos_flag);
    } else {
        process_scale< 400, 20, 32, 8000>(p2, gtb, gtl, mind, tile - 2000, cls_s, iou_s, dfl_s, pos_flag);
    }

    // ---------- block reduction (4 warps) ----------
    int cnt = __popc(__ballot_sync(0xffffffffu, pos_flag));
    #pragma unroll
    for (int o = 16; o > 0; o >>= 1) {
        cls_s += __shfl_down_sync(0xffffffffu, cls_s, o);
        iou_s += __shfl_down_sync(0xffffffffu, iou_s, o);
        dfl_s += __shfl_down_sync(0xffffffffu, dfl_s, o);
    }

    __shared__ float sc[4], si[4], sd[4];
    __shared__ int   sp[4];
    int lane = threadIdx.x & 31;
    int warp = threadIdx.x >> 5;
    if (lane == 0) { sc[warp] = cls_s; si[warp] = iou_s; sd[warp] = dfl_s; sp[warp] = cnt; }
    __syncthreads();

    if (warp == 0 && lane == 0) {
        cls_s = sc[0] + sc[1] + sc[2] + sc[3];
        iou_s = si[0] + si[1] + si[2] + si[3];
        dfl_s = sd[0] + sd[1] + sd[2] + sd[3];
        cnt   = sp[0] + sp[1] + sp[2] + sp[3];

        atomicAdd(&g_acc[0], (double)cls_s);
        atomicAdd(&g_acc[1], (double)iou_s);
        atomicAdd(&g_acc[2], (double)dfl_s);
        atomicAdd(&g_acc[3], (double)cnt);

        __threadfence();
        unsigned int ticket = atomicAdd(&g_done, 1u);
        if (ticket == gridDim.x - 1) {
            double v0 = atomicAdd(&g_acc[0], 0.0);
            double v1 = atomicAdd(&g_acc[1], 0.0);
            double v2 = atomicAdd(&g_acc[2], 0.0);
            double v3 = atomicAdd(&g_acc[3], 0.0);
            double np = v3 < 1.0 ? 1.0 : v3;
            double total = v0 / np + 7.5 * v1 / np + 1.5 * v2 / (np * 4.0);
            for (int i = 0; i < out_n; ++i) out[i] = (float)total;
            g_acc[0] = 0.0; g_acc[1] = 0.0; g_acc[2] = 0.0; g_acc[3] = 0.0;
            __threadfence();
            g_done = 0u;
        }
    }
}

extern "C" void kernel_launch(void* const* d_in, const int* in_sizes, int n_in,
                              void* d_out, int out_size) {
    const float* p0   = (const float*)d_in[0];
    const float* p1   = (const float*)d_in[1];
    const float* p2   = (const float*)d_in[2];
    const float* gtb  = (const float*)d_in[3];
    const int*   gtl  = (const int*)d_in[4];
    const int*   mind = (const int*)d_in[5];
    float* out = (float*)d_out;

    // 1600 + 400 + 100 = 2100 blocks of 128 threads; single wave at 16 blocks/SM
    yolo_loss_kernel<<<2100, 128>>>(p0, p1, p2, gtb, gtl, mind, out, out_size);
}

// round 16
// speedup vs baseline: 2.6210x; 1.0082x over previous
#include <cuda_runtime.h>

#define NANCH 8400
#define BATCH 32
#define NCLS  80
#define BINS  16
#define LN2   0.69314718f

// [0]=cls_sum [1]=iou_sum [2]=dfl_sum [3]=pos_count
__device__ double g_acc[4];
__device__ unsigned int g_done;

__device__ __forceinline__ float tanh_fast(float x) {
    float y;
    asm("tanh.approx.f32 %0, %1;" : "=f"(y) : "f"(x));
    return y;
}

// returns sigmoid(s)^2 * log2(sigmoid(-s));  focal t=0 elem = -0.75*ln2 * this
__device__ __forceinline__ float cls_neg_raw(float s) {
    float t = tanh_fast(0.5f * s);
    float u = 0.5f - 0.5f * t;           // sigmoid(-s)
    float p = 0.5f + 0.5f * t;           // sigmoid(s)
    return p * p * __log2f(u);
}

template<int HW, int W, int STRIDE, int AOFS>
__device__ __forceinline__ void process_scale(
    const float* __restrict__ p, const float* __restrict__ gtb,
    const int* __restrict__ gtl, const int* __restrict__ mind,
    int tile, float& cls_s, float& iou_s, float& dfl_s, int& pos_flag)
{
    const int tid = threadIdx.x;

    // ================= cls: transposed float4 stream =================
    // warp (tid>>5) = channel group of 20; lane = anchor quad of 4
    {
        const int g = tid >> 5;                 // 0..3
        const int t = tid & 31;                 // 0..31
        const int aq  = tile * 128 + 4 * t;     // quad base anchor (mult of 4)
        const int imq = aq / HW;                // quad never crosses img (HW%4==0)
        const int hwq = aq - imq * HW;

        const float* cb = p + (size_t)imq * 144 * HW + hwq + (size_t)(64 + g * 20) * HW;

        float c0 = 0.f, c1 = 0.f, c2 = 0.f, c3 = 0.f;
        #pragma unroll
        for (int c = 0; c < 20; ++c) {
            float4 v = __ldcs(reinterpret_cast<const float4*>(cb + c * HW));
            c0 += cls_neg_raw(v.x);
            c1 += cls_neg_raw(v.y);
            c2 += cls_neg_raw(v.z);
            c3 += cls_neg_raw(v.w);
        }
        cls_s = ((c0 + c1) + (c2 + c3)) * (-0.75f * LN2);
    }

    // ================= positives: R10 shape, anchor = tile*128+tid =================
    const int i   = tile * 128 + tid;
    const int img = i / HW;
    const int hw  = i - img * HW;
    const int ind = mind[img * NANCH + AOFS + hw];

    if (ind >= 0) {
        pos_flag = 1;
        const float* base  = p + (size_t)img * 144 * HW + hw;
        const float* cbase = base + 64 * HW;
        int lbl = gtl[img * 32 + ind];

        // swap t=0 -> t=1 element on the label channel
        {
            float s = cbase[lbl * HW];
            float t = tanh_fast(0.5f * s);
            float u = 0.5f - 0.5f * t;
            float q = 0.5f + 0.5f * t;
            float elem0 = -0.75f * LN2 * q * q * __log2f(u);
            float elem1 = -0.25f * LN2 * u * u * __log2f(q);
            cls_s += elem1 - elem0;
        }

        const float* tb4 = gtb + (size_t)(img * 32 + ind) * 4;
        float tx1 = tb4[0], ty1 = tb4[1], tx2 = tb4[2], ty2 = tb4[3];

        int wy = hw / W, wx = hw - wy * W;
        float gx = (wx + 0.5f) * (float)STRIDE;
        float gy = (wy + 0.5f) * (float)STRIDE;

        float tgt[4] = { fmaxf(gx - tx1, 0.f), fmaxf(gy - ty1, 0.f),
                         fmaxf(tx2 - gx, 0.f), fmaxf(ty2 - gy, 0.f) };
        float d[4];

        #pragma unroll
        for (int k = 0; k < 4; ++k) {
            float tb = fminf(tgt[k] * (1.f / (float)STRIDE), 15.f - 1e-6f);
            int   lo = (int)tb;
            int   hi = min(lo + 1, BINS - 1);
            float aa = tb - (float)lo;

            float S = 0.f, E = 0.f, vlo = 0.f, vhi = 0.f;
            #pragma unroll
            for (int jj = 0; jj < BINS; ++jj) {
                float v = base[(k * BINS + jj) * HW];
                float e = __expf(v);
                S += e;
                E += e * (float)jj;
                vlo = (jj == lo) ? v : vlo;
                vhi = (jj == hi) ? v : vhi;
            }
            d[k] = __fdividef(E, S) * (float)STRIDE;
            float lS = __logf(S);
            dfl_s -= (1.f - aa) * (vlo - lS) + aa * (vhi - lS);
        }

        float px1 = gx - d[0], py1 = gy - d[1];
        float px2 = gx + d[2], py2 = gy + d[3];
        float ix1 = fmaxf(px1, tx1), iy1 = fmaxf(py1, ty1);
        float ix2 = fminf(px2, tx2), iy2 = fminf(py2, ty2);
        float inter  = fmaxf(ix2 - ix1, 0.f) * fmaxf(iy2 - iy1, 0.f);
        float area_p = fmaxf(px2 - px1, 0.f) * fmaxf(py2 - py1, 0.f);
        float area_t = fmaxf(tx2 - tx1, 0.f) * fmaxf(ty2 - ty1, 0.f);
        float iou = inter / (area_p + area_t - inter + 1e-7f);
        iou_s = 1.f - iou;
    }
}

__global__ void __launch_bounds__(128, 12) yolo_loss_kernel(
    const float* __restrict__ p0, const float* __restrict__ p1, const float* __restrict__ p2,
    const float* __restrict__ gtb, const int* __restrict__ gtl, const int* __restrict__ mind,
    float* __restrict__ out, int out_n)
{
    float cls_s = 0.f, iou_s = 0.f, dfl_s = 0.f;
    int pos_flag = 0;

    // 128-anchor tiles: scale0 = 1600 blocks, scale1 = 400, scale2 = 100
    const int tile = blockIdx.x;
    if (tile < 1600) {
        process_scale<6400, 80,  8, 0>(p0, gtb, gtl, mind, tile,        cls_s, iou_s, dfl_s, pos_flag);
    } else if (tile < 2000) {
        process_scale<1600, 40, 16, 6400>(p1, gtb, gtl, mind, tile - 1600, cls_s, iou_s, dfl_s, pos_flag);
    } else {
        process_scale< 400, 20, 32, 8000>(p2, gtb, gtl, mind, tile - 2000, cls_s, iou_s, dfl_s, pos_flag);
    }

    // ---------- block reduction (4 warps) ----------
    int cnt = __popc(__ballot_sync(0xffffffffu, pos_flag));
    #pragma unroll
    for (int o = 16; o > 0; o >>= 1) {
        cls_s += __shfl_down_sync(0xffffffffu, cls_s, o);
        iou_s += __shfl_down_sync(0xffffffffu, iou_s, o);
        dfl_s += __shfl_down_sync(0xffffffffu, dfl_s, o);
    }

    __shared__ float sc[4], si[4], sd[4];
    __shared__ int   sp[4];
    int lane = threadIdx.x & 31;
    int warp = threadIdx.x >> 5;
    if (lane == 0) { sc[warp] = cls_s; si[warp] = iou_s; sd[warp] = dfl_s; sp[warp] = cnt; }
    __syncthreads();

    if (warp == 0 && lane == 0) {
        cls_s = sc[0] + sc[1] + sc[2] + sc[3];
        iou_s = si[0] + si[1] + si[2] + si[3];
        dfl_s = sd[0] + sd[1] + sd[2] + sd[3];
        cnt   = sp[0] + sp[1] + sp[2] + sp[3];

        atomicAdd(&g_acc[0], (double)cls_s);
        atomicAdd(&g_acc[1], (double)iou_s);
        atomicAdd(&g_acc[2], (double)dfl_s);
        atomicAdd(&g_acc[3], (double)cnt);

        __threadfence();
        unsigned int ticket = atomicAdd(&g_done, 1u);
        if (ticket == gridDim.x - 1) {
            double v0 = atomicAdd(&g_acc[0], 0.0);
            double v1 = atomicAdd(&g_acc[1], 0.0);
            double v2 = atomicAdd(&g_acc[2], 0.0);
            double v3 = atomicAdd(&g_acc[3], 0.0);
            double np = v3 < 1.0 ? 1.0 : v3;
            double total = v0 / np + 7.5 * v1 / np + 1.5 * v2 / (np * 4.0);
            for (int i = 0; i < out_n; ++i) out[i] = (float)total;
            g_acc[0] = 0.0; g_acc[1] = 0.0; g_acc[2] = 0.0; g_acc[3] = 0.0;
            __threadfence();
            g_done = 0u;
        }
    }
}

extern "C" void kernel_launch(void* const* d_in, const int* in_sizes, int n_in,
                              void* d_out, int out_size) {
    const float* p0   = (const float*)d_in[0];
    const float* p1   = (const float*)d_in[1];
    const float* p2   = (const float*)d_in[2];
    const float* gtb  = (const float*)d_in[3];
    const int*   gtl  = (const int*)d_in[4];
    const int*   mind = (const int*)d_in[5];
    float* out = (float*)d_out;

    // 1600 + 400 + 100 = 2100 blocks of 128 threads
    yolo_loss_kernel<<<2100, 128>>>(p0, p1, p2, gtb, gtl, mind, out, out_size);
}